// round 2
// baseline (speedup 1.0000x reference)
#include <cuda_runtime.h>
#include <cstdint>

// ---------------------------------------------------------------------------
// BSplineBasis: out[N,60] = cubic B-spline basis of min-max-normalized x over
// 64 clamped knots. Only <=4 of 60 outputs per row are nonzero (degree 3).
// HBM-store-bound on the 252MB output.
//
// Correctness-critical details (matching the JAX reference bit-for-bit where
// it matters):
//  - xn = (x - min) / (max - min + 1e-8) with IEEE rn ops (no fast-math).
//  - Degree-0 seed is the half-open indicator [t_i, t_{i+1}); when xn rounds
//    to exactly 1.0f (the max element does!), NO interval contains it and the
//    whole row is zero.
//  - Recursion uses the reference's guarded divisions (denom > 0 ? div : 0).
// ---------------------------------------------------------------------------

#define NUM_KNOTS 64
#define DEGREE 3
#define NBASIS (NUM_KNOTS - DEGREE - 1)   // 60

__device__ unsigned g_min_u;
__device__ unsigned g_max_u;

__device__ __forceinline__ unsigned fmap(float f) {
    unsigned u = __float_as_uint(f);
    return (u & 0x80000000u) ? ~u : (u | 0x80000000u);
}
__device__ __forceinline__ float funmap(unsigned u) {
    u = (u & 0x80000000u) ? (u & 0x7FFFFFFFu) : ~u;
    return __uint_as_float(u);
}

__global__ void init_minmax_kernel() {
    g_min_u = 0xFFFFFFFFu;
    g_max_u = 0x00000000u;
}

__global__ void minmax_kernel(const float* __restrict__ x, int n) {
    int tid = blockIdx.x * blockDim.x + threadIdx.x;
    int stride = gridDim.x * blockDim.x;

    unsigned lmin = 0xFFFFFFFFu;
    unsigned lmax = 0x00000000u;

    int n4 = n >> 2;
    const float4* x4 = (const float4*)x;
    for (int i = tid; i < n4; i += stride) {
        float4 v = x4[i];
        unsigned a = fmap(v.x), b = fmap(v.y), c = fmap(v.z), d = fmap(v.w);
        lmin = min(lmin, min(min(a, b), min(c, d)));
        lmax = max(lmax, max(max(a, b), max(c, d)));
    }
    for (int i = (n4 << 2) + tid; i < n; i += stride) {
        unsigned a = fmap(x[i]);
        lmin = min(lmin, a);
        lmax = max(lmax, a);
    }

    #pragma unroll
    for (int off = 16; off > 0; off >>= 1) {
        lmin = min(lmin, __shfl_xor_sync(0xFFFFFFFFu, lmin, off));
        lmax = max(lmax, __shfl_xor_sync(0xFFFFFFFFu, lmax, off));
    }

    __shared__ unsigned smin[32], smax[32];
    int lane = threadIdx.x & 31;
    int wid  = threadIdx.x >> 5;
    if (lane == 0) { smin[wid] = lmin; smax[wid] = lmax; }
    __syncthreads();
    if (wid == 0) {
        int nwarp = (blockDim.x + 31) >> 5;
        lmin = (lane < nwarp) ? smin[lane] : 0xFFFFFFFFu;
        lmax = (lane < nwarp) ? smax[lane] : 0x00000000u;
        #pragma unroll
        for (int off = 16; off > 0; off >>= 1) {
            lmin = min(lmin, __shfl_xor_sync(0xFFFFFFFFu, lmin, off));
            lmax = max(lmax, __shfl_xor_sync(0xFFFFFFFFu, lmax, off));
        }
        if (lane == 0) {
            atomicMin(&g_min_u, lmin);
            atomicMax(&g_max_u, lmax);
        }
    }
}

// Guarded Cox-de Boor coefficient: (num / den) if den > 0 else 0.
__device__ __forceinline__ float guarded_div(float num, float den) {
    return (den > 0.0f) ? __fdiv_rn(num, den) : 0.0f;
}

__global__ void __launch_bounds__(256)
bspline_kernel(const float* __restrict__ x,
               const float* __restrict__ knots,
               float* __restrict__ out, int n) {
    __shared__ float t[NUM_KNOTS];
    if (threadIdx.x < NUM_KNOTS) t[threadIdx.x] = knots[threadIdx.x];
    __syncthreads();

    int row = blockIdx.x * blockDim.x + threadIdx.x;
    if (row >= n) return;

    float xmin = funmap(g_min_u);
    float xmax = funmap(g_max_u);
    // Bit-exact reference normalization: (x - min) / (max - min + 1e-8),
    // forced IEEE round-to-nearest regardless of fast-math flags.
    float den = __fadd_rn(__fsub_rn(xmax, xmin), 1e-8f);
    float xn  = __fdiv_rn(__fsub_rn(x[row], xmin), den);

    // Find span i in [3, 59] with t[i] <= xn < t[i+1]; analytic guess + exact
    // fixup. If xn >= 1.0f no interval contains it (seed = 0 -> zero row).
    int i = DEGREE + (int)(xn * (float)(NUM_KNOTS - 2 * DEGREE - 1));
    i = max(DEGREE, min(i, NUM_KNOTS - DEGREE - 2));
    while (i > DEGREE && xn < t[i]) --i;
    while (i < NUM_KNOTS - DEGREE - 2 && xn >= t[i + 1]) ++i;

    // Degree-0 seed: exact half-open indicator (0 for xn==1.0f -> zero row).
    float seed = (xn >= t[i] && xn < t[i + 1]) ? 1.0f : 0.0f;

    // Reference recursion over the active window j in [i-d, i]:
    //   B_d[j] = L(j,d)*B_{d-1}[j] + R(j,d)*B_{d-1}[j+1]
    //   L = (xn - t[j]) / (t[j+d]  - t[j])    if den > 0 else 0
    //   R = (t[j+d+1]-xn)/(t[j+d+1]- t[j+1])  if den > 0 else 0
    // Bcur[k] holds B_d[i-d+k].
    float Bcur[DEGREE + 1];
    Bcur[0] = seed;
    #pragma unroll
    for (int d = 1; d <= DEGREE; ++d) {
        float Bnew[DEGREE + 1];
        #pragma unroll
        for (int k = 0; k <= d; ++k) {
            int j = i - d + k;
            float L = guarded_div(xn - t[j],         t[j + d]     - t[j]);
            float R = guarded_div(t[j + d + 1] - xn, t[j + d + 1] - t[j + 1]);
            float bl = (k >= 1) ? Bcur[k - 1] : 0.0f;  // B_{d-1}[j]
            float br = (k <= d - 1) ? Bcur[k] : 0.0f;  // B_{d-1}[j+1]
            Bnew[k] = L * bl + R * br;
        }
        #pragma unroll
        for (int k = 0; k <= d; ++k) Bcur[k] = Bnew[k];
    }

    // Write the row: 15 aligned 16B zero stores, then overwrite the 4 active
    // entries (same thread -> ordered; same L2 lines -> no extra DRAM traffic).
    float* o = out + (size_t)row * NBASIS;
    float4* o4 = (float4*)o;
    #pragma unroll
    for (int q = 0; q < NBASIS / 4; ++q)
        o4[q] = make_float4(0.f, 0.f, 0.f, 0.f);

    int c0 = i - DEGREE;
    o[c0 + 0] = Bcur[0];
    o[c0 + 1] = Bcur[1];
    o[c0 + 2] = Bcur[2];
    o[c0 + 3] = Bcur[3];
}

extern "C" void kernel_launch(void* const* d_in, const int* in_sizes, int n_in,
                              void* d_out, int out_size) {
    const float* x     = (const float*)d_in[0];
    const float* knots = (const float*)d_in[1];
    float* out = (float*)d_out;
    int n = in_sizes[0];   // N_ROWS (x is [N,1])

    init_minmax_kernel<<<1, 1>>>();
    minmax_kernel<<<1024, 256>>>(x, n);

    int threads = 256;
    int blocks  = (n + threads - 1) / threads;
    bspline_kernel<<<blocks, threads>>>(x, knots, out, n);
}

// round 3
// speedup vs baseline: 2.0572x; 2.0572x over previous
#include <cuda_runtime.h>
#include <cstdint>

// ---------------------------------------------------------------------------
// BSplineBasis: out[N,60] = cubic B-spline basis of min-max-normalized x.
// Only <=4 of 60 outputs per row are nonzero (degree 3).
// HBM-store-bound (252MB output). Rows are staged in shared memory so the
// global writes are fully coalesced (row = 240B = 15 float4 exactly, so a
// 128-row tile is one contiguous 30720B gmem span).
// ---------------------------------------------------------------------------

#define NUM_KNOTS 64
#define DEGREE 3
#define NBASIS (NUM_KNOTS - DEGREE - 1)   // 60
#define ROWS_PER_BLOCK 128
#define TILE_FLOATS (ROWS_PER_BLOCK * NBASIS)   // 7680 floats = 30720 B
#define TILE_VEC4 (TILE_FLOATS / 4)             // 1920

__device__ unsigned g_min_u;
__device__ unsigned g_max_u;

__device__ __forceinline__ unsigned fmap(float f) {
    unsigned u = __float_as_uint(f);
    return (u & 0x80000000u) ? ~u : (u | 0x80000000u);
}
__device__ __forceinline__ float funmap(unsigned u) {
    u = (u & 0x80000000u) ? (u & 0x7FFFFFFFu) : ~u;
    return __uint_as_float(u);
}

__global__ void init_minmax_kernel() {
    g_min_u = 0xFFFFFFFFu;
    g_max_u = 0x00000000u;
}

__global__ void minmax_kernel(const float* __restrict__ x, int n) {
    int tid = blockIdx.x * blockDim.x + threadIdx.x;
    int stride = gridDim.x * blockDim.x;

    unsigned lmin = 0xFFFFFFFFu;
    unsigned lmax = 0x00000000u;

    int n4 = n >> 2;
    const float4* x4 = (const float4*)x;
    for (int i = tid; i < n4; i += stride) {
        float4 v = x4[i];
        unsigned a = fmap(v.x), b = fmap(v.y), c = fmap(v.z), d = fmap(v.w);
        lmin = min(lmin, min(min(a, b), min(c, d)));
        lmax = max(lmax, max(max(a, b), max(c, d)));
    }
    for (int i = (n4 << 2) + tid; i < n; i += stride) {
        unsigned a = fmap(x[i]);
        lmin = min(lmin, a);
        lmax = max(lmax, a);
    }

    #pragma unroll
    for (int off = 16; off > 0; off >>= 1) {
        lmin = min(lmin, __shfl_xor_sync(0xFFFFFFFFu, lmin, off));
        lmax = max(lmax, __shfl_xor_sync(0xFFFFFFFFu, lmax, off));
    }

    __shared__ unsigned smin[32], smax[32];
    int lane = threadIdx.x & 31;
    int wid  = threadIdx.x >> 5;
    if (lane == 0) { smin[wid] = lmin; smax[wid] = lmax; }
    __syncthreads();
    if (wid == 0) {
        int nwarp = (blockDim.x + 31) >> 5;
        lmin = (lane < nwarp) ? smin[lane] : 0xFFFFFFFFu;
        lmax = (lane < nwarp) ? smax[lane] : 0x00000000u;
        #pragma unroll
        for (int off = 16; off > 0; off >>= 1) {
            lmin = min(lmin, __shfl_xor_sync(0xFFFFFFFFu, lmin, off));
            lmax = max(lmax, __shfl_xor_sync(0xFFFFFFFFu, lmax, off));
        }
        if (lane == 0) {
            atomicMin(&g_min_u, lmin);
            atomicMax(&g_max_u, lmax);
        }
    }
}

__device__ __forceinline__ float guarded_div(float num, float den) {
    return (den > 0.0f) ? __fdiv_rn(num, den) : 0.0f;
}

__global__ void __launch_bounds__(ROWS_PER_BLOCK)
bspline_kernel(const float* __restrict__ x,
               const float* __restrict__ knots,
               float* __restrict__ out, int n) {
    __shared__ float t[NUM_KNOTS];
    __shared__ float tile[TILE_FLOATS];    // 30720 B staging

    if (threadIdx.x < NUM_KNOTS) t[threadIdx.x] = knots[threadIdx.x];

    // Zero the tile (coalesced STS.128).
    float4* tile4 = (float4*)tile;
    #pragma unroll
    for (int q = 0; q < TILE_VEC4 / ROWS_PER_BLOCK; ++q)
        tile4[q * ROWS_PER_BLOCK + threadIdx.x] = make_float4(0.f, 0.f, 0.f, 0.f);
    __syncthreads();

    int row = blockIdx.x * ROWS_PER_BLOCK + threadIdx.x;

    if (row < n) {
        float xmin = funmap(g_min_u);
        float xmax = funmap(g_max_u);
        // Bit-exact reference normalization (forced IEEE rn ops).
        float den = __fadd_rn(__fsub_rn(xmax, xmin), 1e-8f);
        float xn  = __fdiv_rn(__fsub_rn(x[row], xmin), den);

        // Span search: analytic guess + exact fixup against knots.
        int i = DEGREE + (int)(xn * (float)(NUM_KNOTS - 2 * DEGREE - 1));
        i = max(DEGREE, min(i, NUM_KNOTS - DEGREE - 2));
        while (i > DEGREE && xn < t[i]) --i;
        while (i < NUM_KNOTS - DEGREE - 2 && xn >= t[i + 1]) ++i;

        // Degree-0 seed: half-open indicator (0 when xn rounds to 1.0f ->
        // whole row zero, matching the reference's max-element behavior).
        float seed = (xn >= t[i] && xn < t[i + 1]) ? 1.0f : 0.0f;

        // Reference Cox-de Boor recursion on the 4-wide active window.
        float Bcur[DEGREE + 1];
        Bcur[0] = seed;
        #pragma unroll
        for (int d = 1; d <= DEGREE; ++d) {
            float Bnew[DEGREE + 1];
            #pragma unroll
            for (int k = 0; k <= d; ++k) {
                int j = i - d + k;
                float L = guarded_div(xn - t[j],         t[j + d]     - t[j]);
                float R = guarded_div(t[j + d + 1] - xn, t[j + d + 1] - t[j + 1]);
                float bl = (k >= 1) ? Bcur[k - 1] : 0.0f;
                float br = (k <= d - 1) ? Bcur[k] : 0.0f;
                Bnew[k] = L * bl + R * br;
            }
            #pragma unroll
            for (int k = 0; k <= d; ++k) Bcur[k] = Bnew[k];
        }

        // Scatter the 4 nonzeros into the smem tile.
        int base = threadIdx.x * NBASIS + (i - DEGREE);
        tile[base + 0] = Bcur[0];
        tile[base + 1] = Bcur[1];
        tile[base + 2] = Bcur[2];
        tile[base + 3] = Bcur[3];
    }
    __syncthreads();

    // Coalesced tile writeback: the 128-row tile is one contiguous 30720B
    // span of out. Consecutive lanes -> consecutive float4s.
    size_t tile_base = (size_t)blockIdx.x * TILE_FLOATS;
    float4* o4 = (float4*)(out + tile_base);
    int rows_left = n - blockIdx.x * ROWS_PER_BLOCK;
    if (rows_left >= ROWS_PER_BLOCK) {
        #pragma unroll
        for (int q = 0; q < TILE_VEC4 / ROWS_PER_BLOCK; ++q)
            o4[q * ROWS_PER_BLOCK + threadIdx.x] =
                tile4[q * ROWS_PER_BLOCK + threadIdx.x];
    } else {
        int valid4 = rows_left * (NBASIS / 4);
        for (int q = threadIdx.x; q < valid4; q += ROWS_PER_BLOCK)
            o4[q] = tile4[q];
    }
}

extern "C" void kernel_launch(void* const* d_in, const int* in_sizes, int n_in,
                              void* d_out, int out_size) {
    const float* x     = (const float*)d_in[0];
    const float* knots = (const float*)d_in[1];
    float* out = (float*)d_out;
    int n = in_sizes[0];   // N_ROWS (x is [N,1])

    init_minmax_kernel<<<1, 1>>>();
    minmax_kernel<<<1024, 256>>>(x, n);

    int blocks = (n + ROWS_PER_BLOCK - 1) / ROWS_PER_BLOCK;
    bspline_kernel<<<blocks, ROWS_PER_BLOCK>>>(x, knots, out, n);
}

// round 4
// speedup vs baseline: 2.0865x; 1.0142x over previous
#include <cuda_runtime.h>
#include <cstdint>

// ---------------------------------------------------------------------------
// BSplineBasis: out[N,60] = cubic B-spline basis of min-max-normalized x.
// <=4 of 60 outputs per row are nonzero (degree 3). HBM-store-bound (252MB).
//
// Two launches only:
//  1) minmax_partials: fixed 256-block grid, each block writes its partial
//     min/max (plain stores, fully overwritten each run -> deterministic,
//     graph-safe, no init kernel and no atomics).
//  2) bspline: each block reduces the 256 partials (L2-broadcast reads),
//     computes rows, stages a 128-row tile in smem, and writes back fully
//     coalesced with streaming (.cs) 128-bit stores.
// ---------------------------------------------------------------------------

#define NUM_KNOTS 64
#define DEGREE 3
#define NBASIS (NUM_KNOTS - DEGREE - 1)   // 60
#define ROWS_PER_BLOCK 128
#define TILE_FLOATS (ROWS_PER_BLOCK * NBASIS)   // 7680 floats = 30720 B
#define TILE_VEC4 (TILE_FLOATS / 4)             // 1920
#define NPART 256                                // partial-reduction blocks

__device__ unsigned g_pmin[NPART];
__device__ unsigned g_pmax[NPART];

__device__ __forceinline__ unsigned fmap(float f) {
    unsigned u = __float_as_uint(f);
    return (u & 0x80000000u) ? ~u : (u | 0x80000000u);
}
__device__ __forceinline__ float funmap(unsigned u) {
    u = (u & 0x80000000u) ? (u & 0x7FFFFFFFu) : ~u;
    return __uint_as_float(u);
}

__global__ void __launch_bounds__(256)
minmax_partials_kernel(const float* __restrict__ x, int n) {
    int tid = blockIdx.x * blockDim.x + threadIdx.x;
    int stride = gridDim.x * blockDim.x;

    unsigned lmin = 0xFFFFFFFFu;
    unsigned lmax = 0x00000000u;

    int n4 = n >> 2;
    const float4* x4 = (const float4*)x;
    for (int i = tid; i < n4; i += stride) {
        float4 v = x4[i];
        unsigned a = fmap(v.x), b = fmap(v.y), c = fmap(v.z), d = fmap(v.w);
        lmin = min(lmin, min(min(a, b), min(c, d)));
        lmax = max(lmax, max(max(a, b), max(c, d)));
    }
    for (int i = (n4 << 2) + tid; i < n; i += stride) {
        unsigned a = fmap(x[i]);
        lmin = min(lmin, a);
        lmax = max(lmax, a);
    }

    #pragma unroll
    for (int off = 16; off > 0; off >>= 1) {
        lmin = min(lmin, __shfl_xor_sync(0xFFFFFFFFu, lmin, off));
        lmax = max(lmax, __shfl_xor_sync(0xFFFFFFFFu, lmax, off));
    }

    __shared__ unsigned smin[8], smax[8];
    int lane = threadIdx.x & 31;
    int wid  = threadIdx.x >> 5;
    if (lane == 0) { smin[wid] = lmin; smax[wid] = lmax; }
    __syncthreads();
    if (wid == 0) {
        lmin = (lane < 8) ? smin[lane] : 0xFFFFFFFFu;
        lmax = (lane < 8) ? smax[lane] : 0x00000000u;
        #pragma unroll
        for (int off = 4; off > 0; off >>= 1) {
            lmin = min(lmin, __shfl_xor_sync(0xFFFFFFFFu, lmin, off));
            lmax = max(lmax, __shfl_xor_sync(0xFFFFFFFFu, lmax, off));
        }
        if (lane == 0) {
            g_pmin[blockIdx.x] = lmin;   // unconditional overwrite each run
            g_pmax[blockIdx.x] = lmax;
        }
    }
}

__device__ __forceinline__ float guarded_div(float num, float den) {
    return (den > 0.0f) ? __fdiv_rn(num, den) : 0.0f;
}

__global__ void __launch_bounds__(ROWS_PER_BLOCK)
bspline_kernel(const float* __restrict__ x,
               const float* __restrict__ knots,
               float* __restrict__ out, int n) {
    __shared__ float t[NUM_KNOTS];
    __shared__ float tile[TILE_FLOATS];     // 30720 B staging
    __shared__ unsigned rmin[4], rmax[4];
    __shared__ unsigned bmin, bmax;

    if (threadIdx.x < NUM_KNOTS) t[threadIdx.x] = knots[threadIdx.x];

    // Per-block reduction of the 256 global partials (L2-broadcast loads).
    {
        unsigned a = min(g_pmin[threadIdx.x], g_pmin[threadIdx.x + 128]);
        unsigned b = max(g_pmax[threadIdx.x], g_pmax[threadIdx.x + 128]);
        #pragma unroll
        for (int off = 16; off > 0; off >>= 1) {
            a = min(a, __shfl_xor_sync(0xFFFFFFFFu, a, off));
            b = max(b, __shfl_xor_sync(0xFFFFFFFFu, b, off));
        }
        int lane = threadIdx.x & 31;
        int wid  = threadIdx.x >> 5;
        if (lane == 0) { rmin[wid] = a; rmax[wid] = b; }
    }

    // Zero the tile (coalesced STS.128).
    float4* tile4 = (float4*)tile;
    #pragma unroll
    for (int q = 0; q < TILE_VEC4 / ROWS_PER_BLOCK; ++q)
        tile4[q * ROWS_PER_BLOCK + threadIdx.x] = make_float4(0.f, 0.f, 0.f, 0.f);
    __syncthreads();

    if (threadIdx.x == 0) {
        bmin = min(min(rmin[0], rmin[1]), min(rmin[2], rmin[3]));
        bmax = max(max(rmax[0], rmax[1]), max(rmax[2], rmax[3]));
    }
    __syncthreads();

    int row = blockIdx.x * ROWS_PER_BLOCK + threadIdx.x;

    if (row < n) {
        float xmin = funmap(bmin);
        float xmax = funmap(bmax);
        // Bit-exact reference normalization (forced IEEE rn ops).
        float den = __fadd_rn(__fsub_rn(xmax, xmin), 1e-8f);
        float xn  = __fdiv_rn(__fsub_rn(x[row], xmin), den);

        // Span search: analytic guess + exact fixup against knots.
        int i = DEGREE + (int)(xn * (float)(NUM_KNOTS - 2 * DEGREE - 1));
        i = max(DEGREE, min(i, NUM_KNOTS - DEGREE - 2));
        while (i > DEGREE && xn < t[i]) --i;
        while (i < NUM_KNOTS - DEGREE - 2 && xn >= t[i + 1]) ++i;

        // Degree-0 seed: half-open indicator (0 when xn rounds to 1.0f ->
        // whole row zero, matching the reference's max-element behavior).
        float seed = (xn >= t[i] && xn < t[i + 1]) ? 1.0f : 0.0f;

        // Reference Cox-de Boor recursion on the 4-wide active window.
        float Bcur[DEGREE + 1];
        Bcur[0] = seed;
        #pragma unroll
        for (int d = 1; d <= DEGREE; ++d) {
            float Bnew[DEGREE + 1];
            #pragma unroll
            for (int k = 0; k <= d; ++k) {
                int j = i - d + k;
                float L = guarded_div(xn - t[j],         t[j + d]     - t[j]);
                float R = guarded_div(t[j + d + 1] - xn, t[j + d + 1] - t[j + 1]);
                float bl = (k >= 1) ? Bcur[k - 1] : 0.0f;
                float br = (k <= d - 1) ? Bcur[k] : 0.0f;
                Bnew[k] = L * bl + R * br;
            }
            #pragma unroll
            for (int k = 0; k <= d; ++k) Bcur[k] = Bnew[k];
        }

        // Scatter the 4 nonzeros into the smem tile.
        int base = threadIdx.x * NBASIS + (i - DEGREE);
        tile[base + 0] = Bcur[0];
        tile[base + 1] = Bcur[1];
        tile[base + 2] = Bcur[2];
        tile[base + 3] = Bcur[3];
    }
    __syncthreads();

    // Coalesced, streaming tile writeback: the 128-row tile is one contiguous
    // 30720B span of out. Consecutive lanes -> consecutive float4s. .cs hint
    // evicts the write-only output from L2 early (252MB stream vs 126MB L2).
    size_t tile_base = (size_t)blockIdx.x * TILE_FLOATS;
    float4* o4 = (float4*)(out + tile_base);
    int rows_left = n - blockIdx.x * ROWS_PER_BLOCK;
    if (rows_left >= ROWS_PER_BLOCK) {
        #pragma unroll
        for (int q = 0; q < TILE_VEC4 / ROWS_PER_BLOCK; ++q)
            __stcs(&o4[q * ROWS_PER_BLOCK + threadIdx.x],
                   tile4[q * ROWS_PER_BLOCK + threadIdx.x]);
    } else {
        int valid4 = rows_left * (NBASIS / 4);
        for (int q = threadIdx.x; q < valid4; q += ROWS_PER_BLOCK)
            __stcs(&o4[q], tile4[q]);
    }
}

extern "C" void kernel_launch(void* const* d_in, const int* in_sizes, int n_in,
                              void* d_out, int out_size) {
    const float* x     = (const float*)d_in[0];
    const float* knots = (const float*)d_in[1];
    float* out = (float*)d_out;
    int n = in_sizes[0];   // N_ROWS (x is [N,1])

    minmax_partials_kernel<<<NPART, 256>>>(x, n);

    int blocks = (n + ROWS_PER_BLOCK - 1) / ROWS_PER_BLOCK;
    bspline_kernel<<<blocks, ROWS_PER_BLOCK>>>(x, knots, out, n);
}

// round 5
// speedup vs baseline: 2.4240x; 1.1617x over previous
#include <cuda_runtime.h>
#include <cstdint>

// ---------------------------------------------------------------------------
// BSplineBasis: out[N,60] = cubic B-spline basis of min-max-normalized x.
// <=4 of 60 outputs per row are nonzero (degree 3). HBM-store-bound (252MB).
//
// R5 structure:
//  1) minmax_partials: 256 blocks write partial min/max (plain overwriting
//     stores -> deterministic, graph-safe, no init kernel).
//  2) bspline: per block of 128 threads/rows:
//     - precompute guarded reciprocal tables for all Cox-de Boor denominators
//       (knot-only, 186 floats) -> recursion is divide-free,
//     - each thread composes its own 240B row in smem (15 zero STS.128 + <=2
//       composed overwrites; conflict-free: 60 = 28 mod 32 tiles all banks),
//     - one elected thread TMA-bulk-copies the contiguous 30720B tile to gmem
//       (no per-thread LDS/STG readback at all).
// ---------------------------------------------------------------------------

#define NUM_KNOTS 64
#define DEGREE 3
#define NBASIS (NUM_KNOTS - DEGREE - 1)   // 60
#define ROWS_PER_BLOCK 128
#define TILE_FLOATS (ROWS_PER_BLOCK * NBASIS)   // 7680 floats = 30720 B
#define NPART 256
// inv table layout: d=1 at [0,63), d=2 at [63,125), d=3 at [125,186)
#define INV1 0
#define INV2 63
#define INV3 125
#define INV_TOTAL 186

__device__ unsigned g_pmin[NPART];
__device__ unsigned g_pmax[NPART];

__device__ __forceinline__ unsigned fmap(float f) {
    unsigned u = __float_as_uint(f);
    return (u & 0x80000000u) ? ~u : (u | 0x80000000u);
}
__device__ __forceinline__ float funmap(unsigned u) {
    u = (u & 0x80000000u) ? (u & 0x7FFFFFFFu) : ~u;
    return __uint_as_float(u);
}

__global__ void __launch_bounds__(256)
minmax_partials_kernel(const float* __restrict__ x, int n) {
    int tid = blockIdx.x * blockDim.x + threadIdx.x;
    int stride = gridDim.x * blockDim.x;

    unsigned lmin = 0xFFFFFFFFu;
    unsigned lmax = 0x00000000u;

    int n4 = n >> 2;
    const float4* x4 = (const float4*)x;
    for (int i = tid; i < n4; i += stride) {
        float4 v = x4[i];
        unsigned a = fmap(v.x), b = fmap(v.y), c = fmap(v.z), d = fmap(v.w);
        lmin = min(lmin, min(min(a, b), min(c, d)));
        lmax = max(lmax, max(max(a, b), max(c, d)));
    }
    for (int i = (n4 << 2) + tid; i < n; i += stride) {
        unsigned a = fmap(x[i]);
        lmin = min(lmin, a);
        lmax = max(lmax, a);
    }

    #pragma unroll
    for (int off = 16; off > 0; off >>= 1) {
        lmin = min(lmin, __shfl_xor_sync(0xFFFFFFFFu, lmin, off));
        lmax = max(lmax, __shfl_xor_sync(0xFFFFFFFFu, lmax, off));
    }

    __shared__ unsigned smin[8], smax[8];
    int lane = threadIdx.x & 31;
    int wid  = threadIdx.x >> 5;
    if (lane == 0) { smin[wid] = lmin; smax[wid] = lmax; }
    __syncthreads();
    if (wid == 0) {
        lmin = (lane < 8) ? smin[lane] : 0xFFFFFFFFu;
        lmax = (lane < 8) ? smax[lane] : 0x00000000u;
        #pragma unroll
        for (int off = 4; off > 0; off >>= 1) {
            lmin = min(lmin, __shfl_xor_sync(0xFFFFFFFFu, lmin, off));
            lmax = max(lmax, __shfl_xor_sync(0xFFFFFFFFu, lmax, off));
        }
        if (lane == 0) {
            g_pmin[blockIdx.x] = lmin;
            g_pmax[blockIdx.x] = lmax;
        }
    }
}

__global__ void __launch_bounds__(ROWS_PER_BLOCK)
bspline_kernel(const float* __restrict__ x,
               const float* __restrict__ knots,
               float* __restrict__ out, int n) {
    __shared__ __align__(16) float tile[TILE_FLOATS];   // 30720 B
    __shared__ float t[NUM_KNOTS];
    __shared__ float inv[INV_TOTAL];
    __shared__ unsigned rmin[4], rmax[4];

    int tid = threadIdx.x;
    int row = blockIdx.x * ROWS_PER_BLOCK + tid;

    // Issue the x load early.
    float xv = (row < n) ? x[row] : 0.0f;

    // Knots to smem.
    if (tid < NUM_KNOTS) t[tid] = __ldg(&knots[tid]);

    // Guarded reciprocal tables straight from gmem knots (no smem dependency).
    for (int f = tid; f < INV_TOTAL; f += ROWS_PER_BLOCK) {
        int d, j;
        if (f < INV2)      { d = 1; j = f; }
        else if (f < INV3) { d = 2; j = f - INV2; }
        else               { d = 3; j = f - INV3; }
        float den = __ldg(&knots[j + d]) - __ldg(&knots[j]);
        inv[f] = (den > 0.0f) ? __fdiv_rn(1.0f, den) : 0.0f;
    }

    // Reduce the 256 global partials (each thread folds 2, warp-reduce).
    {
        unsigned a = min(g_pmin[tid], g_pmin[tid + 128]);
        unsigned b = max(g_pmax[tid], g_pmax[tid + 128]);
        #pragma unroll
        for (int off = 16; off > 0; off >>= 1) {
            a = min(a, __shfl_xor_sync(0xFFFFFFFFu, a, off));
            b = max(b, __shfl_xor_sync(0xFFFFFFFFu, b, off));
        }
        if ((tid & 31) == 0) { rmin[tid >> 5] = a; rmax[tid >> 5] = b; }
    }
    __syncthreads();

    if (row < n) {
        unsigned bmin = min(min(rmin[0], rmin[1]), min(rmin[2], rmin[3]));
        unsigned bmax = max(max(rmax[0], rmax[1]), max(rmax[2], rmax[3]));
        float xmin = funmap(bmin);
        float xmax = funmap(bmax);

        // Bit-exact reference normalization (this div feeds the interval
        // comparisons -> must round exactly like the reference; the xn==1.0f
        // max element produces an all-zero row).
        float den = __fadd_rn(__fsub_rn(xmax, xmin), 1e-8f);
        float xn  = __fdiv_rn(__fsub_rn(xv, xmin), den);

        // Span search: analytic guess + exact fixup.
        int i = DEGREE + (int)(xn * (float)(NUM_KNOTS - 2 * DEGREE - 1));
        i = max(DEGREE, min(i, NUM_KNOTS - DEGREE - 2));
        while (i > DEGREE && xn < t[i]) --i;
        while (i < NUM_KNOTS - DEGREE - 2 && xn >= t[i + 1]) ++i;

        float seed = (xn >= t[i] && xn < t[i + 1]) ? 1.0f : 0.0f;

        // Divide-free Cox-de Boor recursion on the 4-wide active window.
        //   L(j,d) = (xn - t[j])       * inv_d[j]
        //   R(j,d) = (t[j+d+1] - xn)   * inv_d[j+1]
        float Bcur[DEGREE + 1];
        Bcur[0] = seed;
        #pragma unroll
        for (int d = 1; d <= DEGREE; ++d) {
            const int base = (d == 1) ? INV1 : (d == 2) ? INV2 : INV3;
            float Bnew[DEGREE + 1];
            #pragma unroll
            for (int k = 0; k <= d; ++k) {
                int j = i - d + k;
                float L = (xn - t[j])         * inv[base + j];
                float R = (t[j + d + 1] - xn) * inv[base + j + 1];
                float bl = (k >= 1) ? Bcur[k - 1] : 0.0f;
                float br = (k <= d - 1) ? Bcur[k] : 0.0f;
                Bnew[k] = L * bl + R * br;
            }
            #pragma unroll
            for (int k = 0; k <= d; ++k) Bcur[k] = Bnew[k];
        }

        // Compose this thread's own 240B row in smem: 15 zero STS.128, then
        // overwrite the 1-2 float4s containing the active window. Same-thread
        // same-address stores are program-ordered. Lane stride 240B tiles all
        // 32 banks per 8-lane phase (60 mod 32 = 28) -> conflict-free.
        float4* myrow = (float4*)(tile + tid * NBASIS);
        #pragma unroll
        for (int q = 0; q < NBASIS / 4; ++q)
            myrow[q] = make_float4(0.f, 0.f, 0.f, 0.f);

        int c0 = i - DEGREE;          // [0, 56]
        int q0 = c0 >> 2;
        int r  = c0 & 3;
        float4 f0, f1;
        f0.x = (r == 0) ? Bcur[0] : 0.f;
        f0.y = (r == 0) ? Bcur[1] : (r == 1) ? Bcur[0] : 0.f;
        f0.z = (r == 0) ? Bcur[2] : (r == 1) ? Bcur[1] : (r == 2) ? Bcur[0] : 0.f;
        f0.w = (r == 0) ? Bcur[3] : (r == 1) ? Bcur[2] : (r == 2) ? Bcur[1] : Bcur[0];
        f1.x = (r == 1) ? Bcur[3] : (r == 2) ? Bcur[2] : (r == 3) ? Bcur[1] : 0.f;
        f1.y = (r == 2) ? Bcur[3] : (r == 3) ? Bcur[2] : 0.f;
        f1.z = (r == 3) ? Bcur[3] : 0.f;
        f1.w = 0.f;
        myrow[q0] = f0;
        if (r != 0) myrow[q0 + 1] = f1;   // r>0 implies q0+1 <= 14
    }

    // Make generic-proxy smem writes visible to the async (TMA) proxy.
    asm volatile("fence.proxy.async.shared::cta;" ::: "memory");
    __syncthreads();

    // One bulk async copy: the whole tile is a contiguous span of `out`.
    if (tid == 0) {
        int rows_left = n - blockIdx.x * ROWS_PER_BLOCK;
        int valid = (rows_left < ROWS_PER_BLOCK) ? rows_left : ROWS_PER_BLOCK;
        if (valid > 0) {
            unsigned bytes = (unsigned)valid * (NBASIS * 4);   // multiple of 16
            float* gdst = out + (size_t)blockIdx.x * TILE_FLOATS;
            unsigned saddr;
            asm volatile("{ .reg .u64 a; cvta.to.shared.u64 a, %1; cvt.u32.u64 %0, a; }"
                         : "=r"(saddr) : "l"(tile));
            asm volatile("cp.async.bulk.global.shared::cta.bulk_group [%0], [%1], %2;"
                         :: "l"(gdst), "r"(saddr), "r"(bytes) : "memory");
            asm volatile("cp.async.bulk.commit_group;" ::: "memory");
            asm volatile("cp.async.bulk.wait_group 0;" ::: "memory");
        }
    }
    __syncthreads();   // keep smem alive until the copy is done
}

extern "C" void kernel_launch(void* const* d_in, const int* in_sizes, int n_in,
                              void* d_out, int out_size) {
    const float* x     = (const float*)d_in[0];
    const float* knots = (const float*)d_in[1];
    float* out = (float*)d_out;
    int n = in_sizes[0];   // N_ROWS (x is [N,1])

    minmax_partials_kernel<<<NPART, 256>>>(x, n);

    int blocks = (n + ROWS_PER_BLOCK - 1) / ROWS_PER_BLOCK;
    bspline_kernel<<<blocks, ROWS_PER_BLOCK>>>(x, knots, out, n);
}